// round 17
// baseline (speedup 1.0000x reference)
#include <cuda_runtime.h>
#include <cuda_bf16.h>
#include <cuda_fp16.h>
#include <cstdint>
#include <cstddef>

// ---------------------------------------------------------------------------
// Problem constants
// ---------------------------------------------------------------------------
#define BATCH   4
#define CC      512
#define NTOK    4096
#define NROWS   (BATCH*NTOK)
#define HHEADS  8
#define HD      64
#define CTX_S   77
#define CTX_SP  128       // padded S for ctx (cols >= 77 exact zeros)
#define CTX_D   768
#define GEO_S   256
#define GEO_D   512
#define FFN_D   2048
#define LN_EPS  1e-5f

static inline int ceil_div(int a, int b) { return (a + b - 1) / b; }

// ---------------------------------------------------------------------------
// Scratch (static device globals) — fp16 pairs packed as uint32
// ---------------------------------------------------------------------------
__device__ __align__(16) uint32_t g_xn [4194304];   // LN output (fp16)
__device__ __align__(16) uint32_t g_q  [4194304];   // Q (fp16)
__device__ __align__(16) uint32_t g_k  [262144];    // K proj (fp16)
__device__ __align__(16) uint32_t g_vt [262144];    // V^T per head (fp16)
__device__ __align__(16) uint32_t g_a  [4194304];   // attn out (fp16)
__device__ __align__(16) uint32_t g_p  [16777216];  // FFN hidden (fp16)
__device__ __align__(16) uint32_t g_ct [118272];    // ctx input (fp16)
__device__ __align__(16) uint32_t g_geo[262144];    // geo input (fp16)
__device__ __align__(16) uint32_t g_wt [2228224];   // weights^T (fp16)
__device__ float g_t  [(size_t)NROWS * CC];         // residual stream (fp32)
__device__ float g_v  [(size_t)BATCH * GEO_S * CC];
__device__ float g_big[(size_t)NROWS * CC];         // t0 transpose temp

// word offsets into g_wt
#define WT2_CWQ 0
#define WT2_CWO 131072
#define WT2_GWQ 262144
#define WT2_GWO 393216
#define WT2_W1  524288
#define WT2_W2  1048576
#define WT2_CWK 1572864
#define WT2_CWV 1769472
#define WT2_GWK 1966080
#define WT2_GWV 2097152

__device__ __forceinline__ float gelu_exact(float x) {
    return 0.5f * x * (1.0f + erff(x * 0.70710678118654752440f));
}

// ---------------------------------------------------------------------------
// helpers
// ---------------------------------------------------------------------------
__device__ __forceinline__ uint32_t smem_u32(const void* p) {
    uint32_t a;
    asm("{ .reg .u64 t; cvta.to.shared.u64 t, %1; cvt.u32.u64 %0, t; }" : "=r"(a) : "l"(p));
    return a;
}
__device__ __forceinline__ uint32_t pack_h2(float x, float y) {
    __half2 h = __floats2half2_rn(x, y);
    return *reinterpret_cast<uint32_t*>(&h);
}
__device__ __forceinline__ void mma16816(float c[4], uint32_t a0, uint32_t a1, uint32_t a2,
                                         uint32_t a3, uint32_t b0, uint32_t b1) {
    asm volatile(
        "mma.sync.aligned.m16n8k16.row.col.f32.f16.f16.f32 "
        "{%0,%1,%2,%3}, {%4,%5,%6,%7}, {%8,%9}, {%0,%1,%2,%3};"
        : "+f"(c[0]), "+f"(c[1]), "+f"(c[2]), "+f"(c[3])
        : "r"(a0), "r"(a1), "r"(a2), "r"(a3), "r"(b0), "r"(b1));
}
__device__ __forceinline__ void ldsm4(uint32_t& r0, uint32_t& r1, uint32_t& r2, uint32_t& r3,
                                      uint32_t addr) {
    asm volatile("ldmatrix.sync.aligned.m8n8.x4.shared.b16 {%0,%1,%2,%3}, [%4];"
                 : "=r"(r0), "=r"(r1), "=r"(r2), "=r"(r3) : "r"(addr));
}
// swizzled word offset, 16-word rows (GEMM tiles)
__device__ __forceinline__ int swzg(int row, int kg) {
    return row * 16 + (((kg ^ ((row >> 1) & 3))) << 2);
}
// swizzled word offset, 32-word rows (Q/K attn tiles)
__device__ __forceinline__ int swzg32(int row, int kg) {
    return row * 32 + (((kg ^ (row & 7))) << 2);
}
// swizzled word offset, W-group rows (VT tiles), W >= 8
__device__ __forceinline__ int swzgW(int row, int kg, int W) {
    return row * (W * 4) + (((kg ^ (row & 7))) << 2);
}
__device__ __forceinline__ void cpa16(uint32_t dst, const uint32_t* src, bool ok) {
    int sz = ok ? 16 : 0;
    asm volatile("cp.async.cg.shared.global [%0], [%1], 16, %2;"
                 :: "r"(dst), "l"(src), "r"(sz) : "memory");
}

// ---------------------------------------------------------------------------
// fp16 single-pass HMMA GEMM (unchanged)
// ---------------------------------------------------------------------------
template <int NT, int EPI, int OUT, bool GN, bool GM>
__global__ void __launch_bounds__(256) hgemm_kernel(
    const uint32_t* __restrict__ A, int lda2, long long sAb2, long long sAh2,
    const uint32_t* __restrict__ B, int ldb2, long long sBb2, long long sBh2,
    float* __restrict__ Cf, uint32_t* __restrict__ Ch,
    int ldc, long long sCb, long long sChh,
    const float* __restrict__ bias,
    int M, int N, int K, float alpha, int H)
{
    constexpr int MI = (NT == 128) ? 4 : 2;
    constexpr int AW = 2048;
    constexpr int BW = NT * 16;
    constexpr int O_A = 0, O_B = AW;
    constexpr int STG = AW + BW;
    extern __shared__ uint32_t sm[];

    {
        int z = blockIdx.z;
        int bb = z / H, hh = z - bb * H;
        A += bb * sAb2 + hh * sAh2;
        B += bb * sBb2 + hh * sBh2;
        long long co = bb * sCb + hh * sChh;
        if (OUT == 0) Cf += co;
        else Ch += (co >> 1);
    }

    const int tid  = threadIdx.x;
    const int wid  = tid >> 5, lane = tid & 31;
    const int g    = lane >> 2, t4 = lane & 3;
    const int wm   = (NT == 128) ? (wid >> 2) : (wid >> 1);
    const int wn   = (NT == 128) ? (wid & 3)  : (wid & 1);
    const int m0   = blockIdx.y * 128;
    const int n0   = blockIdx.x * NT;
    const uint32_t smb = smem_u32(sm);

    auto issue = [&](int ch, int stg) {
        const int k0w = ch * 16;
        const uint32_t base = smb + (uint32_t)stg * STG * 4;
        {
            int r  = tid >> 1;
            int gr = m0 + r;
            bool ok = !GM || (gr < M);
            if (GM) gr = min(gr, M - 1);
            const uint32_t* sa = A + (size_t)gr * lda2 + k0w;
            #pragma unroll
            for (int e = 0; e < 2; ++e) {
                int grp = (tid & 1) * 2 + e;
                cpa16(base + (O_A + swzg(r, grp)) * 4, sa + grp * 4, ok);
            }
        }
        if (NT == 128) {
            int r  = tid >> 1;
            int gr = n0 + r;
            bool ok = !GN || (gr < N);
            if (GN) gr = min(gr, N - 1);
            const uint32_t* sb = B + (size_t)gr * ldb2 + k0w;
            #pragma unroll
            for (int e = 0; e < 2; ++e) {
                int grp = (tid & 1) * 2 + e;
                cpa16(base + (O_B + swzg(r, grp)) * 4, sb + grp * 4, ok);
            }
        } else {
            int r = tid >> 2, grp = tid & 3;
            const uint32_t* sb = B + (size_t)(n0 + r) * ldb2 + k0w;
            cpa16(base + (O_B + swzg(r, grp)) * 4, sb + grp * 4, true);
        }
        asm volatile("cp.async.commit_group;" ::: "memory");
    };

    float acc[MI][4][4] = {};
    const int nch = K >> 5;

    issue(0, 0);
    if (nch > 1) issue(1, 1);

    const int a_rin = ((lane >> 3) & 1) * 8 + (lane & 7);
    const int a_kg  = lane >> 4;
    const int b_blk = lane >> 4;
    const int b_kg  = (lane >> 3) & 1;
    const int b_rin = lane & 7;

    for (int ch = 0; ch < nch; ++ch) {
        if (ch + 1 < nch) {
            asm volatile("cp.async.wait_group 1;" ::: "memory");
        } else {
            asm volatile("cp.async.wait_group 0;" ::: "memory");
        }
        __syncthreads();
        if (ch + 2 < nch) issue(ch + 2, (ch + 2) % 3);

        const uint32_t stb = smb + (uint32_t)(ch % 3) * STG * 4;
        #pragma unroll
        for (int ks = 0; ks < 2; ++ks) {
            uint32_t af[MI][4], bf[4][2];
            #pragma unroll
            for (int mi = 0; mi < MI; ++mi) {
                int rr = wm * (MI * 16) + mi * 16 + a_rin;
                int kg = ks * 2 + a_kg;
                ldsm4(af[mi][0], af[mi][1], af[mi][2], af[mi][3],
                      stb + (O_A + swzg(rr, kg)) * 4);
            }
            #pragma unroll
            for (int nb = 0; nb < 2; ++nb) {
                int nr = wn * 32 + (nb * 2 + b_blk) * 8 + b_rin;
                int kg = ks * 2 + b_kg;
                ldsm4(bf[nb * 2][0], bf[nb * 2][1], bf[nb * 2 + 1][0],
                      bf[nb * 2 + 1][1], stb + (O_B + swzg(nr, kg)) * 4);
            }
            #pragma unroll
            for (int mi = 0; mi < MI; ++mi)
                #pragma unroll
                for (int ni = 0; ni < 4; ++ni)
                    mma16816(acc[mi][ni], af[mi][0], af[mi][1], af[mi][2],
                             af[mi][3], bf[ni][0], bf[ni][1]);
        }
    }

    const int ldc2 = ldc >> 1;
    #pragma unroll
    for (int mi = 0; mi < MI; ++mi) {
        #pragma unroll
        for (int ni = 0; ni < 4; ++ni) {
            int row0 = m0 + wm * (MI * 16) + mi * 16 + g;
            int col  = n0 + wn * 32 + ni * 8 + 2 * t4;
            float* c = acc[mi][ni];
            #pragma unroll
            for (int h = 0; h < 2; ++h) {
                int row = row0 + h * 8;
                if (GM && row >= M) continue;
                float v0 = c[2 * h] * alpha, v1 = c[2 * h + 1] * alpha;
                if (EPI == 2) {
                    v0 = gelu_exact(v0 + bias[col]);
                    v1 = gelu_exact(v1 + bias[col + 1]);
                }
                if (OUT == 0) {
                    size_t off = (size_t)row * ldc + col;
                    if (EPI == 3) {
                        v0 += bias[col]     + Cf[off];
                        v1 += bias[col + 1] + Cf[off + 1];
                    }
                    if (GN) {
                        if (col < N)     Cf[off]     = v0;
                        if (col + 1 < N) Cf[off + 1] = v1;
                    } else {
                        float2 o; o.x = v0; o.y = v1;
                        *reinterpret_cast<float2*>(&Cf[off]) = o;
                    }
                } else {
                    size_t o = (size_t)row * ldc2 + (col >> 1);
                    Ch[o] = pack_h2(v0, v1);
                }
            }
        }
    }
}

template <int NT, int EPI, int OUT, bool GN, bool GM>
static void L(const uint32_t* A, int lda2, long long sAb2, long long sAh2,
              const uint32_t* B, int ldb2, long long sBb2, long long sBh2,
              float* Cf, uint32_t* Ch, int ldc,
              long long sCb, long long sChh, const float* bias,
              int M, int N, int K, float alpha, int batches, int H) {
    constexpr int STG = 2048 + NT * 16;
    const int smem = 3 * STG * 4;
    cudaFuncSetAttribute(hgemm_kernel<NT, EPI, OUT, GN, GM>,
                         cudaFuncAttributeMaxDynamicSharedMemorySize, smem);
    dim3 grid(ceil_div(N, NT), ceil_div(M, 128), batches);
    hgemm_kernel<NT, EPI, OUT, GN, GM><<<grid, 256, smem>>>(
        A, lda2, sAb2, sAh2, B, ldb2, sBb2, sBh2,
        Cf, Ch, ldc, sCb, sChh, bias, M, N, K, alpha, H);
}

// ---------------------------------------------------------------------------
// Fully-fused attention: A_out = softmax(0.125 Q K^T) @ V   (per b,h, 64-row tile)
// Q,K: fp16 proj buffers (rows x 256 words, head at word hh*32).
// VT: per-(b,h) V^T fp16, HD x SP/2 words. A_out written like Q layout.
// Grid: (NTOK/64, B*H). 256 threads, warps wm(2) x wn(4).
// ---------------------------------------------------------------------------
template <int S, int SP>
__global__ void __launch_bounds__(256) attn_fused_kernel(
    const uint32_t* __restrict__ Q, const uint32_t* __restrict__ K,
    const uint32_t* __restrict__ VT, uint32_t* __restrict__ A)
{
    constexpr int NI  = SP / 32;          // n8 score tiles per warp
    constexpr int W   = SP / 8;           // 16B groups per VT row
    constexpr int O_Q = 0;                // 64 x 32 words
    constexpr int O_K = 2048;             // SP x 32 words
    constexpr int O_V = O_K + SP * 32;    // 64 x SP/2 words
    constexpr int O_R = O_V + 64 * (SP / 2);  // softmax red 64*4 floats
    extern __shared__ uint32_t sm[];

    const int bh = blockIdx.y;
    const int bb = bh >> 3, hh = bh & 7;
    const int m0 = blockIdx.x * 64;
    const uint32_t* Qp = Q + (size_t)bb * NTOK * 256 + (size_t)hh * 32;
    const uint32_t* Kp = K + (size_t)bb * S * 256 + (size_t)hh * 32;
    const uint32_t* Vp = VT + (size_t)bh * HD * (SP / 2);
    uint32_t* Ap = A + (size_t)bb * NTOK * 256 + (size_t)hh * 32;

    const int tid  = threadIdx.x;
    const int wid  = tid >> 5, lane = tid & 31;
    const int g    = lane >> 2, t4 = lane & 3;
    const int wm   = wid >> 2, wn = wid & 3;
    const uint32_t smb = smem_u32(sm);

    // ---- fills: Q (512), K (SP*8), VT (64*W)
    #pragma unroll
    for (int t = tid; t < 512; t += 256) {
        int r = t >> 3, kg = t & 7;
        cpa16(smb + (O_Q + swzg32(r, kg)) * 4,
              Qp + (size_t)(m0 + r) * 256 + kg * 4, true);
    }
    for (int t = tid; t < SP * 8; t += 256) {
        int s = t >> 3, kg = t & 7;
        bool ok = (s < S);
        int sc = ok ? s : (S - 1);
        cpa16(smb + (O_K + swzg32(s, kg)) * 4,
              Kp + (size_t)sc * 256 + kg * 4, ok);
    }
    for (int t = tid; t < 64 * W; t += 256) {
        int d = t / W, kg = t % W;
        cpa16(smb + (O_V + swzgW(d, kg, W)) * 4,
              Vp + (size_t)d * (SP / 2) + kg * 4, true);
    }
    asm volatile("cp.async.commit_group;" ::: "memory");
    asm volatile("cp.async.wait_group 0;" ::: "memory");
    __syncthreads();

    const int a_rin = ((lane >> 3) & 1) * 8 + (lane & 7);
    const int a_kg  = lane >> 4;
    const int b_blk = lane >> 4;
    const int b_kg  = (lane >> 3) & 1;
    const int b_rin = lane & 7;

    // ---- phase 1: scores 64 x SP (per-warp cols wn*NI*8 ..)
    float acc[2][NI][4] = {};
    #pragma unroll
    for (int ks = 0; ks < 4; ++ks) {
        uint32_t af[2][4], bf[NI][2];
        #pragma unroll
        for (int mi = 0; mi < 2; ++mi) {
            int rr = wm * 32 + mi * 16 + a_rin;
            ldsm4(af[mi][0], af[mi][1], af[mi][2], af[mi][3],
                  smb + (O_Q + swzg32(rr, ks * 2 + a_kg)) * 4);
        }
        #pragma unroll
        for (int nb = 0; nb < NI / 2; ++nb) {
            int nr = wn * NI * 8 + (nb * 2 + b_blk) * 8 + b_rin;
            ldsm4(bf[nb * 2][0], bf[nb * 2][1], bf[nb * 2 + 1][0],
                  bf[nb * 2 + 1][1], smb + (O_K + swzg32(nr, ks * 2 + b_kg)) * 4);
        }
        #pragma unroll
        for (int mi = 0; mi < 2; ++mi)
            #pragma unroll
            for (int ni = 0; ni < NI; ++ni)
                mma16816(acc[mi][ni], af[mi][0], af[mi][1], af[mi][2],
                         af[mi][3], bf[ni][0], bf[ni][1]);
    }

    // ---- softmax
    float* red = reinterpret_cast<float*>(sm + O_R);
    float lmax[4] = {-1e30f, -1e30f, -1e30f, -1e30f};
    #pragma unroll
    for (int mi = 0; mi < 2; ++mi)
        #pragma unroll
        for (int ni = 0; ni < NI; ++ni)
            #pragma unroll
            for (int j = 0; j < 4; ++j) {
                float v = acc[mi][ni][j] * 0.125f;
                if (S < SP) {
                    int col = wn * NI * 8 + ni * 8 + t4 * 2 + (j & 1);
                    if (col >= S) v = -1e30f;
                }
                acc[mi][ni][j] = v;
                int ri = mi * 2 + (j >> 1);
                lmax[ri] = fmaxf(lmax[ri], v);
            }
    #pragma unroll
    for (int o = 1; o <= 2; o <<= 1)
        #pragma unroll
        for (int ri = 0; ri < 4; ++ri)
            lmax[ri] = fmaxf(lmax[ri], __shfl_xor_sync(0xffffffffu, lmax[ri], o));
    if (t4 == 0) {
        #pragma unroll
        for (int ri = 0; ri < 4; ++ri) {
            int row = wm * 32 + (ri >> 1) * 16 + (ri & 1) * 8 + g;
            red[row * 4 + wn] = lmax[ri];
        }
    }
    __syncthreads();
    float gmx[4];
    #pragma unroll
    for (int ri = 0; ri < 4; ++ri) {
        int row = wm * 32 + (ri >> 1) * 16 + (ri & 1) * 8 + g;
        gmx[ri] = fmaxf(fmaxf(red[row * 4], red[row * 4 + 1]),
                        fmaxf(red[row * 4 + 2], red[row * 4 + 3]));
    }
    __syncthreads();
    float lsum[4] = {0.f, 0.f, 0.f, 0.f};
    #pragma unroll
    for (int mi = 0; mi < 2; ++mi)
        #pragma unroll
        for (int ni = 0; ni < NI; ++ni)
            #pragma unroll
            for (int j = 0; j < 4; ++j) {
                int ri = mi * 2 + (j >> 1);
                float e = __expf(acc[mi][ni][j] - gmx[ri]);
                acc[mi][ni][j] = e;
                lsum[ri] += e;
            }
    #pragma unroll
    for (int o = 1; o <= 2; o <<= 1)
        #pragma unroll
        for (int ri = 0; ri < 4; ++ri)
            lsum[ri] += __shfl_xor_sync(0xffffffffu, lsum[ri], o);
    if (t4 == 0) {
        #pragma unroll
        for (int ri = 0; ri < 4; ++ri) {
            int row = wm * 32 + (ri >> 1) * 16 + (ri & 1) * 8 + g;
            red[row * 4 + wn] = lsum[ri];
        }
    }
    __syncthreads();
    float inv[4];
    #pragma unroll
    for (int ri = 0; ri < 4; ++ri) {
        int row = wm * 32 + (ri >> 1) * 16 + (ri & 1) * 8 + g;
        inv[ri] = 1.0f / (red[row * 4] + red[row * 4 + 1] +
                          red[row * 4 + 2] + red[row * 4 + 3]);
    }

    // ---- phase 2: P @ V over this warp's SP slice (K split across wn)
    float acc2[2][8][4] = {};
    #pragma unroll
    for (int kb = 0; kb < NI / 2; ++kb) {
        int kglob = wn * (NI / 2) + kb;     // global k16 block in SP
        uint32_t af[2][4];
        #pragma unroll
        for (int mi = 0; mi < 2; ++mi) {
            float i0 = inv[mi * 2 + 0], i1 = inv[mi * 2 + 1];
            af[mi][0] = pack_h2(acc[mi][2 * kb][0] * i0, acc[mi][2 * kb][1] * i0);
            af[mi][1] = pack_h2(acc[mi][2 * kb][2] * i1, acc[mi][2 * kb][3] * i1);
            af[mi][2] = pack_h2(acc[mi][2 * kb + 1][0] * i0, acc[mi][2 * kb + 1][1] * i0);
            af[mi][3] = pack_h2(acc[mi][2 * kb + 1][2] * i1, acc[mi][2 * kb + 1][3] * i1);
        }
        uint32_t bf[8][2];
        #pragma unroll
        for (int nb = 0; nb < 4; ++nb) {
            int nr = (nb * 2 + b_blk) * 8 + b_rin;
            ldsm4(bf[nb * 2][0], bf[nb * 2][1], bf[nb * 2 + 1][0],
                  bf[nb * 2 + 1][1],
                  smb + (O_V + swzgW(nr, kglob * 2 + b_kg, W)) * 4);
        }
        #pragma unroll
        for (int mi = 0; mi < 2; ++mi)
            #pragma unroll
            for (int nt = 0; nt < 8; ++nt)
                mma16816(acc2[mi][nt], af[mi][0], af[mi][1], af[mi][2],
                         af[mi][3], bf[nt][0], bf[nt][1]);
    }

    // ---- phase 3: reduce partials across wn warps (reuse Q/K smem region)
    float* ored = reinterpret_cast<float*>(sm);   // 64 x 64 floats
    __syncthreads();
    #pragma unroll
    for (int s = 0; s < 4; ++s) {
        if (wn == s) {
            #pragma unroll
            for (int mi = 0; mi < 2; ++mi)
                #pragma unroll
                for (int nt = 0; nt < 8; ++nt)
                    #pragma unroll
                    for (int j = 0; j < 4; ++j) {
                        int row = wm * 32 + mi * 16 + (j >> 1) * 8 + g;
                        int col = nt * 8 + t4 * 2 + (j & 1);
                        if (s == 0) ored[row * 64 + col] = acc2[mi][nt][j];
                        else        ored[row * 64 + col] += acc2[mi][nt][j];
                    }
        }
        __syncthreads();
    }

    // ---- store A fp16: 64 rows x 32 words
    {
        int row = tid >> 2, wq = (tid & 3) * 8;
        #pragma unroll
        for (int jj = 0; jj < 8; ++jj) {
            int w = wq + jj;
            Ap[(size_t)(m0 + row) * 256 + w] =
                pack_h2(ored[row * 64 + 2 * w], ored[row * 64 + 2 * w + 1]);
        }
    }
}

template <int S, int SP>
static void launch_attn(const uint32_t* Q, const uint32_t* K,
                        const uint32_t* VT, uint32_t* A) {
    const int smem = (2048 + SP * 32 + 64 * (SP / 2) + 256) * 4;
    cudaFuncSetAttribute(attn_fused_kernel<S, SP>,
                         cudaFuncAttributeMaxDynamicSharedMemorySize, smem);
    dim3 grid(NTOK / 64, BATCH * HHEADS);
    attn_fused_kernel<S, SP><<<grid, 256, smem>>>(Q, K, VT, A);
}

// ---------------------------------------------------------------------------
// fp32 transpose (x in/out)
// ---------------------------------------------------------------------------
__global__ void transpose_kernel(const float* __restrict__ in, float* __restrict__ out,
                                 int R, int Ccol) {
    __shared__ float tile[32][33];
    int b = blockIdx.z;
    const float* ip = in  + (size_t)b * R * Ccol;
    float*       op = out + (size_t)b * R * Ccol;
    int j0 = blockIdx.x * 32, i0 = blockIdx.y * 32;
    int tx = threadIdx.x, ty = threadIdx.y;
    #pragma unroll
    for (int k = 0; k < 32; k += 8) tile[ty + k][tx] = ip[(size_t)(i0 + ty + k) * Ccol + j0 + tx];
    __syncthreads();
    #pragma unroll
    for (int k = 0; k < 32; k += 8) op[(size_t)(j0 + ty + k) * R + i0 + tx] = tile[tx][ty + k];
}

// ---------------------------------------------------------------------------
// One-shot weight prep (10 transpose tasks -> fp16 packed)
// ---------------------------------------------------------------------------
struct PrepArgs { const float* src[10]; };

__global__ void prep_weights(PrepArgs a, uint32_t* __restrict__ wt) {
    const int starts[11] = {0, 256, 512, 768, 1024, 1280, 1536, 1920, 2304, 3328, 4352};
    const int Rt[10] = {512, 512, 512, 512, 512, 512, 768, 768, 512, 2048};
    const int Ct[10] = {512, 512, 512, 512, 512, 512, 512, 512, 2048, 512};
    const int Ot[10] = {WT2_CWQ, WT2_CWO, WT2_GWQ, WT2_GWO, WT2_GWK, WT2_GWV,
                        WT2_CWK, WT2_CWV, WT2_W1, WT2_W2};
    int b = blockIdx.x, t = 0;
    while (b >= starts[t + 1]) ++t;
    int lb = b - starts[t];
    int R = Rt[t], C = Ct[t], bx = C / 32;
    int j0 = (lb % bx) * 32, i0 = (lb / bx) * 32;
    const float* in = a.src[t];
    uint32_t* oh = wt + Ot[t];

    __shared__ float tile[32][33];
    int tid = threadIdx.x;
    int tx = tid & 31, ty = tid >> 5;
    #pragma unroll
    for (int k = 0; k < 32; k += 8)
        tile[ty + k][tx] = in[(size_t)(i0 + ty + k) * C + j0 + tx];
    __syncthreads();
    int R2 = R >> 1;
    #pragma unroll
    for (int rep = 0; rep < 2; ++rep) {
        int idx = tid + rep * 256;
        int i2 = idx & 15, j = idx >> 4;
        size_t o = (size_t)(j0 + j) * R2 + (i0 >> 1) + i2;
        oh[o] = pack_h2(tile[2 * i2][j], tile[2 * i2 + 1][j]);
    }
}

// elementwise fp32 -> fp16 pairs
__global__ void cvt_pack(const float* __restrict__ in, uint32_t* __restrict__ oh, int nw) {
    int w = blockIdx.x * 256 + threadIdx.x;
    if (w >= nw) return;
    float2 f = reinterpret_cast<const float2*>(in)[w];
    oh[w] = pack_h2(f.x, f.y);
}

// ---------------------------------------------------------------------------
// LayerNorm single (HL: fp16 out)
// ---------------------------------------------------------------------------
__global__ void ln_kernel(const float* __restrict__ in,
                          const float* __restrict__ gamma,
                          const float* __restrict__ beta,
                          uint32_t* __restrict__ oh) {
    int row = blockIdx.x;
    const float4* rin = reinterpret_cast<const float4*>(in + (size_t)row * CC);
    int t = threadIdx.x;
    float4 v = rin[t];
    float s  = v.x + v.y + v.z + v.w;
    float ss = v.x*v.x + v.y*v.y + v.z*v.z + v.w*v.w;
    #pragma unroll
    for (int o = 16; o > 0; o >>= 1) {
        s  += __shfl_xor_sync(0xffffffffu, s,  o);
        ss += __shfl_xor_sync(0xffffffffu, ss, o);
    }
    __shared__ float shs[4], shss[4];
    int warp = t >> 5, lane = t & 31;
    if (lane == 0) { shs[warp] = s; shss[warp] = ss; }
    __syncthreads();
    s  = shs[0] + shs[1] + shs[2] + shs[3];
    ss = shss[0] + shss[1] + shss[2] + shss[3];
    float mu  = s * (1.0f / CC);
    float var = ss * (1.0f / CC) - mu * mu;
    float rs  = rsqrtf(var + LN_EPS);
    float4 g4 = reinterpret_cast<const float4*>(gamma)[t];
    float4 b4 = reinterpret_cast<const float4*>(beta)[t];
    float ox = (v.x - mu) * rs * g4.x + b4.x;
    float oy = (v.y - mu) * rs * g4.y + b4.y;
    float oz = (v.z - mu) * rs * g4.z + b4.z;
    float ow = (v.w - mu) * rs * g4.w + b4.w;
    size_t w = (size_t)row * (CC / 2) + t * 2;
    oh[w]     = pack_h2(ox, oy);
    oh[w + 1] = pack_h2(oz, ow);
}

// ---------------------------------------------------------------------------
// Fused first LN pair: t = t0 + LN1(t0) (fp32), xn = LN2(t) (fp16)
// ---------------------------------------------------------------------------
__global__ void ln_dual_kernel(const float* __restrict__ in,
                               const float* __restrict__ g1, const float* __restrict__ b1,
                               const float* __restrict__ g2, const float* __restrict__ b2,
                               float* __restrict__ outf, uint32_t* __restrict__ oh) {
    int row = blockIdx.x;
    const float4* rin = reinterpret_cast<const float4*>(in + (size_t)row * CC);
    int t = threadIdx.x;
    int warp = t >> 5, lane = t & 31;
    __shared__ float shs[4], shss[4];
    float4 v = rin[t];

    // pass 1: LN1 + residual add
    float s  = v.x + v.y + v.z + v.w;
    float ss = v.x*v.x + v.y*v.y + v.z*v.z + v.w*v.w;
    #pragma unroll
    for (int o = 16; o > 0; o >>= 1) {
        s  += __shfl_xor_sync(0xffffffffu, s,  o);
        ss += __shfl_xor_sync(0xffffffffu, ss, o);
    }
    if (lane == 0) { shs[warp] = s; shss[warp] = ss; }
    __syncthreads();
    s  = shs[0] + shs[1] + shs[2] + shs[3];
    ss = shss[0] + shss[1] + shss[2] + shss[3];
    float mu  = s * (1.0f / CC);
    float var = ss * (1.0f / CC) - mu * mu;
    float rs  = rsqrtf(var + LN_EPS);
    float4 G = reinterpret_cast<const float4*>(g1)[t];
    float4 Bb = reinterpret_cast<const float4*>(b1)[t];
    float4 r;
    r.x = v.x + (v.x - mu) * rs * G.x + Bb.x;
    r.y = v.y + (v.y - mu) * rs * G.y + Bb.y;
    r.z = v.z + (v.z - mu) * rs * G.z + Bb.z;
    r.w = v.w + (v.w - mu) * rs * G.w + Bb.w;
    reinterpret_cast<float4*>(outf + (size_t)row * CC)[t] = r;

    // pass 2: LN2 of r -> fp16
    float s2  = r.x + r.y + r.z + r.w;
    float ss2 = r.x*r.x + r.y*r.y + r.z*r.z + r.w*r.w;
    #pragma unroll
    for (int o = 16; o > 0; o >>= 1) {
        s2  += __shfl_xor_sync(0xffffffffu, s2,  o);
        ss2 += __shfl_xor_sync(0xffffffffu, ss2, o);
    }
    __syncthreads();
    if (lane == 0) { shs[warp] = s2; shss[warp] = ss2; }
    __syncthreads();
    s2  = shs[0] + shs[1] + shs[2] + shs[3];
    ss2 = shss[0] + shss[1] + shss[2] + shss[3];
    float mu2  = s2 * (1.0f / CC);
    float var2 = ss2 * (1.0f / CC) - mu2 * mu2;
    float rs2  = rsqrtf(var2 + LN_EPS);
    float4 G2 = reinterpret_cast<const float4*>(g2)[t];
    float4 B2 = reinterpret_cast<const float4*>(b2)[t];
    float ox = (r.x - mu2) * rs2 * G2.x + B2.x;
    float oy = (r.y - mu2) * rs2 * G2.y + B2.y;
    float oz = (r.z - mu2) * rs2 * G2.z + B2.z;
    float ow = (r.w - mu2) * rs2 * G2.w + B2.w;
    size_t w = (size_t)row * (CC / 2) + t * 2;
    oh[w]     = pack_h2(ox, oy);
    oh[w + 1] = pack_h2(oz, ow);
}

// ---------------------------------------------------------------------------
// V (B*S x CC fp32) -> per-head V^T fp16 (32 x HD x SP/2 words), zero-padded
// ---------------------------------------------------------------------------
template <int S, int SP>
__global__ void vt_build_h(const float* __restrict__ v, uint32_t* __restrict__ vth) {
    int bh = blockIdx.x;
    int b = bh >> 3, h = bh & 7;
    const float* vb = v + (size_t)b * S * CC + h * 64;
    uint32_t* oh = vth + (size_t)bh * HD * (SP / 2);
    for (int idx = threadIdx.x; idx < HD * (SP / 2); idx += blockDim.x) {
        int d = idx / (SP / 2), sw = idx % (SP / 2);
        int s = 2 * sw;
        float x = (s     < S) ? vb[(size_t)s       * CC + d] : 0.0f;
        float y = (s + 1 < S) ? vb[(size_t)(s + 1) * CC + d] : 0.0f;
        oh[idx] = pack_h2(x, y);
    }
}

// ---------------------------------------------------------------------------
// Entry
// ---------------------------------------------------------------------------
extern "C" void kernel_launch(void* const* d_in, const int* in_sizes, int n_in,
                              void* d_out, int out_size) {
    const float* x    = (const float*)d_in[0];
    const float* ctx  = (const float*)d_in[1];
    const float* geo  = (const float*)d_in[2];
    const float* g1 = (const float*)d_in[3],  *b1 = (const float*)d_in[4];
    const float* g2 = (const float*)d_in[5],  *b2 = (const float*)d_in[6];
    const float* g3 = (const float*)d_in[7],  *b3 = (const float*)d_in[8];
    const float* g4 = (const float*)d_in[9],  *b4 = (const float*)d_in[10];
    const float* cWq = (const float*)d_in[11], *cWk = (const float*)d_in[12];
    const float* cWv = (const float*)d_in[13], *cWo = (const float*)d_in[14];
    const float* cbo = (const float*)d_in[15];
    const float* gWq = (const float*)d_in[16], *gWk = (const float*)d_in[17];
    const float* gWv = (const float*)d_in[18], *gWo = (const float*)d_in[19];
    const float* gbo = (const float*)d_in[20];
    const float* W1  = (const float*)d_in[21], *bf1 = (const float*)d_in[22];
    const float* W2  = (const float*)d_in[23], *bf2 = (const float*)d_in[24];
    float* out = (float*)d_out;

    float *t_d, *v_d, *big_d;
    uint32_t *xn, *q, *k, *vt, *a, *p, *ct, *geo16, *wt;
    cudaGetSymbolAddress((void**)&t_d,  g_t);
    cudaGetSymbolAddress((void**)&v_d,  g_v);
    cudaGetSymbolAddress((void**)&big_d, g_big);
    cudaGetSymbolAddress((void**)&xn, g_xn);
    cudaGetSymbolAddress((void**)&q,  g_q);
    cudaGetSymbolAddress((void**)&k,  g_k);
    cudaGetSymbolAddress((void**)&vt, g_vt);
    cudaGetSymbolAddress((void**)&a,  g_a);
    cudaGetSymbolAddress((void**)&p,  g_p);
    cudaGetSymbolAddress((void**)&ct, g_ct);
    cudaGetSymbolAddress((void**)&geo16, g_geo);
    cudaGetSymbolAddress((void**)&wt, g_wt);

    // weight prep + input packs
    {
        PrepArgs pa;
        pa.src[0] = cWq; pa.src[1] = cWo; pa.src[2] = gWq; pa.src[3] = gWo;
        pa.src[4] = gWk; pa.src[5] = gWv; pa.src[6] = cWk; pa.src[7] = cWv;
        pa.src[8] = W1;  pa.src[9] = W2;
        prep_weights<<<4352, 256>>>(pa, wt);
    }
    {
        int nwc = BATCH * CTX_S * CTX_D / 2;
        cvt_pack<<<ceil_div(nwc, 256), 256>>>(ctx, ct, nwc);
    }
    {
        dim3 grid(NTOK / 32, CC / 32, BATCH);
        transpose_kernel<<<grid, dim3(32, 8)>>>(x, big_d, CC, NTOK);
    }
    // fused: t = t0 + LN1(t0), xn = LN2(t)
    ln_dual_kernel<<<NROWS, 128>>>(big_d, g1, b1, g2, b2, t_d, xn);

    // ================= context cross-attention (S=77, SP=128) =================
    L<128, 0, 2, false, false>(xn, 256, 0, 0,
        wt + WT2_CWQ, 256, 0, 0,
        nullptr, q, CC, 0, 0, nullptr, NROWS, CC, CC, 1.0f, 1, 1);
    L<128, 0, 2, false, true>(ct, 384, 0, 0,
        wt + WT2_CWK, 384, 0, 0,
        nullptr, k, CC, 0, 0, nullptr, BATCH * CTX_S, CC, CTX_D, 1.0f, 1, 1);
    L<128, 0, 0, false, true>(ct, 384, 0, 0,
        wt + WT2_CWV, 384, 0, 0,
        v_d, nullptr, CC, 0, 0, nullptr, BATCH * CTX_S, CC, CTX_D, 1.0f, 1, 1);
    vt_build_h<CTX_S, CTX_SP><<<32, 256>>>(v_d, vt);
    launch_attn<CTX_S, CTX_SP>(q, k, vt, a);
    L<128, 3, 0, false, false>(a, 256, 0, 0,
        wt + WT2_CWO, 256, 0, 0,
        t_d, nullptr, CC, 0, 0, cbo, NROWS, CC, CC, 1.0f, 1, 1);

    // ================= geometry cross-attention (S=256) =================
    {
        int nwg = BATCH * GEO_S * GEO_D / 2;
        cvt_pack<<<ceil_div(nwg, 256), 256>>>(geo, geo16, nwg);
    }
    ln_kernel<<<NROWS, 128>>>(t_d, g3, b3, xn);
    L<128, 0, 2, false, false>(xn, 256, 0, 0,
        wt + WT2_GWQ, 256, 0, 0,
        nullptr, q, CC, 0, 0, nullptr, NROWS, CC, CC, 1.0f, 1, 1);
    L<128, 0, 2, false, false>(geo16, 256, 0, 0,
        wt + WT2_GWK, 256, 0, 0,
        nullptr, k, CC, 0, 0, nullptr, BATCH * GEO_S, CC, GEO_D, 1.0f, 1, 1);
    L<128, 0, 0, false, false>(geo16, 256, 0, 0,
        wt + WT2_GWV, 256, 0, 0,
        v_d, nullptr, CC, 0, 0, nullptr, BATCH * GEO_S, CC, GEO_D, 1.0f, 1, 1);
    vt_build_h<GEO_S, GEO_S><<<32, 256>>>(v_d, vt);
    launch_attn<GEO_S, GEO_S>(q, k, vt, a);
    L<128, 3, 0, false, false>(a, 256, 0, 0,
        wt + WT2_GWO, 256, 0, 0,
        t_d, nullptr, CC, 0, 0, gbo, NROWS, CC, CC, 1.0f, 1, 1);

    // ================= FFN =================
    ln_kernel<<<NROWS, 128>>>(t_d, g4, b4, xn);
    L<128, 2, 2, false, false>(xn, 256, 0, 0,
        wt + WT2_W1, 256, 0, 0,
        nullptr, p, FFN_D, 0, 0, bf1, NROWS, FFN_D, CC, 1.0f, 1, 1);
    L<128, 3, 0, false, false>(p, 1024, 0, 0,
        wt + WT2_W2, 1024, 0, 0,
        t_d, nullptr, CC, 0, 0, bf2, NROWS, CC, FFN_D, 1.0f, 1, 1);

    // ---- transpose back
    {
        dim3 grid(CC / 32, NTOK / 32, BATCH);
        transpose_kernel<<<grid, dim3(32, 8)>>>(t_d, out, NTOK, CC);
    }
}